// round 2
// baseline (speedup 1.0000x reference)
#include <cuda_runtime.h>

// Problem constants: B=1, T=4096, C=768, H=12, D=64
#define T_SEQ 4096
#define C_DIM 768
#define H_NUM 12
#define D_DIM 64

// Scratch (allocation-free: __device__ globals)
__device__ float g_q[H_NUM * D_DIM * T_SEQ];  // [h][d][t], pre-scaled by 1/8
__device__ float g_k[H_NUM * D_DIM * T_SEQ];  // [h][d][t]
__device__ float g_v[H_NUM * T_SEQ * D_DIM];  // [h][t][d]
__device__ float g_y[T_SEQ * C_DIM];          // [t][h*64+d]

// ---------------- packed f32x2 helpers ----------------
__device__ __forceinline__ unsigned long long pack2(float lo, float hi) {
    unsigned long long r;
    asm("mov.b64 %0, {%1,%2};" : "=l"(r) : "f"(lo), "f"(hi));
    return r;
}
__device__ __forceinline__ void unpack2(unsigned long long v, float& lo, float& hi) {
    asm("mov.b64 {%0,%1}, %2;" : "=f"(lo), "=f"(hi) : "l"(v));
}
__device__ __forceinline__ unsigned long long ffma2(unsigned long long a,
                                                    unsigned long long b,
                                                    unsigned long long c) {
    unsigned long long d;
    asm("fma.rn.f32x2 %0, %1, %2, %3;" : "=l"(d) : "l"(a), "l"(b), "l"(c));
    return d;
}
__device__ __forceinline__ unsigned long long mul2(unsigned long long a,
                                                   unsigned long long b) {
    unsigned long long d;
    asm("mul.rn.f32x2 %0, %1, %2;" : "=l"(d) : "l"(a), "l"(b));
    return d;
}

// ---------------- SGEMM: C = A[MxK] @ B[KxN] + bias ----------------
// MODE 0: epilogue scatters into g_q (scaled 1/8, [h][d][t]), g_k ([h][d][t]), g_v ([h][t][d])
// MODE 1: epilogue writes Cout[row*N+col] = acc + bias[col]
template <int MODE>
__global__ __launch_bounds__(256) void sgemm_kernel(
    const float* __restrict__ A, const float* __restrict__ B,
    const float* __restrict__ bias, float* __restrict__ Cout,
    int M, int N, int K) {
    __shared__ float As[16][132];  // [k][m], padded
    __shared__ float Bs[16][128];  // [k][n]

    const int tid = threadIdx.x;
    const int m0 = blockIdx.y * 128;
    const int n0 = blockIdx.x * 128;
    const int ty = tid / 16, tx = tid % 16;
    const int rowbase = ty * 8;

    unsigned long long acc[4][8];
#pragma unroll
    for (int i = 0; i < 4; i++)
#pragma unroll
        for (int j = 0; j < 8; j++) acc[i][j] = 0ull;

    const int ar = tid / 4, ac = tid % 4;   // A load: m = ar(+64), k = ac*4..+3
    const int br = tid / 32, bc = tid % 32; // B load: k = br(+8), n = bc*4..+3

    for (int k0 = 0; k0 < K; k0 += 16) {
#pragma unroll
        for (int p = 0; p < 2; p++) {
            int m = p * 64 + ar;
            float4 av = *(const float4*)&A[(size_t)(m0 + m) * K + k0 + ac * 4];
            As[ac * 4 + 0][m] = av.x;
            As[ac * 4 + 1][m] = av.y;
            As[ac * 4 + 2][m] = av.z;
            As[ac * 4 + 3][m] = av.w;
        }
#pragma unroll
        for (int p = 0; p < 2; p++) {
            int kk = p * 8 + br;
            *(float4*)&Bs[kk][bc * 4] =
                *(const float4*)&B[(size_t)(k0 + kk) * N + n0 + bc * 4];
        }
        __syncthreads();
#pragma unroll
        for (int k = 0; k < 16; k++) {
            ulonglong2 a01 = *(const ulonglong2*)&As[k][rowbase];
            ulonglong2 a23 = *(const ulonglong2*)&As[k][rowbase + 4];
            unsigned long long ap[4] = {a01.x, a01.y, a23.x, a23.y};
            float4 b0 = *(const float4*)&Bs[k][tx * 4];
            float4 b1 = *(const float4*)&Bs[k][64 + tx * 4];
            unsigned long long bb[8] = {
                pack2(b0.x, b0.x), pack2(b0.y, b0.y), pack2(b0.z, b0.z), pack2(b0.w, b0.w),
                pack2(b1.x, b1.x), pack2(b1.y, b1.y), pack2(b1.z, b1.z), pack2(b1.w, b1.w)};
#pragma unroll
            for (int i = 0; i < 4; i++)
#pragma unroll
                for (int j = 0; j < 8; j++)
                    acc[i][j] = ffma2(ap[i], bb[j], acc[i][j]);
        }
        __syncthreads();
    }

    // epilogue
#pragma unroll
    for (int i = 0; i < 4; i++) {
        float lo[8], hi[8];
#pragma unroll
        for (int j = 0; j < 8; j++) unpack2(acc[i][j], lo[j], hi[j]);
        int r0 = m0 + rowbase + 2 * i;  // rows r0 (lo) and r0+1 (hi)
        if (MODE == 1) {
            int c0 = n0 + tx * 4;
            int c1 = n0 + 64 + tx * 4;
            float b00 = bias[c0], b01 = bias[c0 + 1], b02 = bias[c0 + 2], b03 = bias[c0 + 3];
            float b10 = bias[c1], b11 = bias[c1 + 1], b12 = bias[c1 + 2], b13 = bias[c1 + 3];
            float4 v;
            v.x = lo[0] + b00; v.y = lo[1] + b01; v.z = lo[2] + b02; v.w = lo[3] + b03;
            *(float4*)&Cout[(size_t)r0 * N + c0] = v;
            v.x = lo[4] + b10; v.y = lo[5] + b11; v.z = lo[6] + b12; v.w = lo[7] + b13;
            *(float4*)&Cout[(size_t)r0 * N + c1] = v;
            v.x = hi[0] + b00; v.y = hi[1] + b01; v.z = hi[2] + b02; v.w = hi[3] + b03;
            *(float4*)&Cout[(size_t)(r0 + 1) * N + c0] = v;
            v.x = hi[4] + b10; v.y = hi[5] + b11; v.z = hi[6] + b12; v.w = hi[7] + b13;
            *(float4*)&Cout[(size_t)(r0 + 1) * N + c1] = v;
        } else {
#pragma unroll
            for (int j = 0; j < 8; j++) {
                int col = (j < 4) ? (n0 + tx * 4 + j) : (n0 + 64 + tx * 4 + (j - 4));
                float bv = bias[col];
                int which = col / C_DIM;
                int c = col % C_DIM;
                int h = c >> 6, dd = c & 63;
#pragma unroll
                for (int half = 0; half < 2; half++) {
                    int row = r0 + half;
                    float val = ((half == 0) ? lo[j] : hi[j]) + bv;
                    if (which == 0) {
                        g_q[(size_t)(h * D_DIM + dd) * T_SEQ + row] = val * 0.125f;
                    } else if (which == 1) {
                        g_k[(size_t)(h * D_DIM + dd) * T_SEQ + row] = val;
                    } else {
                        g_v[(size_t)(h * T_SEQ + row) * D_DIM + dd] = val;
                    }
                }
            }
        }
    }
}

// ---------------- Flash attention (causal), 64x64 tiles ----------------
// Block b handles q-blocks b and 63-b for head blockIdx.y -> 65 tile-units each.
__global__ __launch_bounds__(256) void flash_kernel() {
    __shared__ float Qs[64 * 64];   // [d][m]
    __shared__ float KPs[64 * 64];  // K as [d][n]; later P as [m][n]
    __shared__ float Vs[64 * 64];   // [n][dv]

    const int tid = threadIdx.x;
    const int h = blockIdx.y;
    const int ty = tid / 16, tx = tid % 16;
    const int lr = tid / 16, lq = tid % 16;  // load mapping

#pragma unroll 1
    for (int pass = 0; pass < 2; pass++) {
        const int qb = (pass == 0) ? (int)blockIdx.x : 63 - (int)blockIdx.x;
        const int qm0 = qb * 64;

        __syncthreads();
#pragma unroll
        for (int p = 0; p < 4; p++) {
            int d = p * 16 + lr;
            *(float4*)&Qs[d * 64 + lq * 4] =
                *(const float4*)&g_q[(size_t)(h * D_DIM + d) * T_SEQ + qm0 + lq * 4];
        }

        float mi[4], li[4];
        unsigned long long o2[4][2];
#pragma unroll
        for (int i = 0; i < 4; i++) {
            mi[i] = -1e30f;
            li[i] = 0.0f;
            o2[i][0] = 0ull;
            o2[i][1] = 0ull;
        }

#pragma unroll 1
        for (int j = 0; j <= qb; j++) {
            const int kv0 = j * 64;
            __syncthreads();
#pragma unroll
            for (int p = 0; p < 4; p++) {
                int d = p * 16 + lr;
                *(float4*)&KPs[d * 64 + lq * 4] =
                    *(const float4*)&g_k[(size_t)(h * D_DIM + d) * T_SEQ + kv0 + lq * 4];
            }
#pragma unroll
            for (int p = 0; p < 4; p++) {
                int n = p * 16 + lr;
                *(float4*)&Vs[n * 64 + lq * 4] =
                    *(const float4*)&g_v[(size_t)(h * T_SEQ + kv0 + n) * D_DIM + lq * 4];
            }
            __syncthreads();

            // GEMM1: S = Q^T-tile . K-tile, rows ty*4..+3, cols tx*4..+3
            unsigned long long s2[2][4];
#pragma unroll
            for (int mp = 0; mp < 2; mp++)
#pragma unroll
                for (int jj = 0; jj < 4; jj++) s2[mp][jj] = 0ull;
#pragma unroll 16
            for (int d = 0; d < 64; d++) {
                ulonglong2 qv = *(const ulonglong2*)&Qs[d * 64 + ty * 4];
                float4 kv = *(const float4*)&KPs[d * 64 + tx * 4];
                unsigned long long kb[4] = {pack2(kv.x, kv.x), pack2(kv.y, kv.y),
                                            pack2(kv.z, kv.z), pack2(kv.w, kv.w)};
#pragma unroll
                for (int jj = 0; jj < 4; jj++) {
                    s2[0][jj] = ffma2(qv.x, kb[jj], s2[0][jj]);
                    s2[1][jj] = ffma2(qv.y, kb[jj], s2[1][jj]);
                }
            }
            float s[4][4];
#pragma unroll
            for (int jj = 0; jj < 4; jj++) {
                unpack2(s2[0][jj], s[0][jj], s[1][jj]);
                unpack2(s2[1][jj], s[2][jj], s[3][jj]);
            }

            if (j == qb) {  // causal mask on diagonal block
#pragma unroll
                for (int i = 0; i < 4; i++)
#pragma unroll
                    for (int jj = 0; jj < 4; jj++)
                        if (tx * 4 + jj > ty * 4 + i) s[i][jj] = -1e30f;
            }

            // online softmax (rows spread over 16 lanes: shfl_xor 1,2,4,8)
#pragma unroll
            for (int i = 0; i < 4; i++) {
                float rm = fmaxf(fmaxf(s[i][0], s[i][1]), fmaxf(s[i][2], s[i][3]));
#pragma unroll
                for (int off = 8; off >= 1; off >>= 1)
                    rm = fmaxf(rm, __shfl_xor_sync(0xffffffffu, rm, off));
                float mnew = fmaxf(mi[i], rm);
                float alpha = __expf(mi[i] - mnew);
                mi[i] = mnew;
                float rs = 0.0f;
#pragma unroll
                for (int jj = 0; jj < 4; jj++) {
                    float p = __expf(s[i][jj] - mnew);
                    s[i][jj] = p;
                    rs += p;
                }
#pragma unroll
                for (int off = 8; off >= 1; off >>= 1)
                    rs += __shfl_xor_sync(0xffffffffu, rs, off);
                li[i] = li[i] * alpha + rs;
                unsigned long long a2 = pack2(alpha, alpha);
                o2[i][0] = mul2(o2[i][0], a2);
                o2[i][1] = mul2(o2[i][1], a2);
            }

            __syncthreads();  // everyone done reading KPs as K
#pragma unroll
            for (int i = 0; i < 4; i++) {
                float4 pv = make_float4(s[i][0], s[i][1], s[i][2], s[i][3]);
                *(float4*)&KPs[(ty * 4 + i) * 64 + tx * 4] = pv;  // P as [m][n]
            }
            __syncthreads();

            // GEMM2: O += P . V, rows ty*4..+3, dv cols tx*4..+3
#pragma unroll 16
            for (int n = 0; n < 64; n++) {
                ulonglong2 vv = *(const ulonglong2*)&Vs[n * 64 + tx * 4];
#pragma unroll
                for (int i = 0; i < 4; i++) {
                    float pi = KPs[(ty * 4 + i) * 64 + n];
                    unsigned long long pb = pack2(pi, pi);
                    o2[i][0] = ffma2(pb, vv.x, o2[i][0]);
                    o2[i][1] = ffma2(pb, vv.y, o2[i][1]);
                }
            }
        }

        // normalize + write y[t][h*64+dv]
#pragma unroll
        for (int i = 0; i < 4; i++) {
            float inv = 1.0f / li[i];
            float a, b, c, d;
            unpack2(o2[i][0], a, b);
            unpack2(o2[i][1], c, d);
            float4 ov = make_float4(a * inv, b * inv, c * inv, d * inv);
            *(float4*)&g_y[(size_t)(qm0 + ty * 4 + i) * C_DIM + h * 64 + tx * 4] = ov;
        }
    }
}

// ---------------- launch ----------------
extern "C" void kernel_launch(void* const* d_in, const int* in_sizes, int n_in,
                              void* d_out, int out_size) {
    const float* x = (const float*)d_in[0];
    // d_in[1] = mask (ignored: causality is hardcoded)
    const float* Wqkv = (const float*)d_in[2];
    const float* bqkv = (const float*)d_in[3];
    const float* Wproj = (const float*)d_in[4];
    const float* bproj = (const float*)d_in[5];
    float* out = (float*)d_out;

    void* yptr = nullptr;
    cudaGetSymbolAddress(&yptr, g_y);

    // 1) QKV projection with scatter epilogue
    sgemm_kernel<0><<<dim3(18, 32), 256>>>(x, Wqkv, bqkv, nullptr,
                                           T_SEQ, 3 * C_DIM, C_DIM);
    // 2) causal flash attention
    flash_kernel<<<dim3(32, H_NUM), 256>>>();
    // 3) output projection
    sgemm_kernel<1><<<dim3(6, 32), 256>>>((const float*)yptr, Wproj, bproj, out,
                                          T_SEQ, C_DIM, C_DIM);
}

// round 5
// speedup vs baseline: 2.2288x; 2.2288x over previous
#include <cuda_runtime.h>
#include <cuda_bf16.h>
#include <cstdint>

typedef __nv_bfloat16 bf16;

#define T_SEQ 4096
#define C_DIM 768
#define H_NUM 12
#define D_DIM 64
#define NQKV  2304

// ---------------- scratch (__device__ globals; no allocation) ----------------
__device__ bf16 g_xhi[T_SEQ * C_DIM], g_xlo[T_SEQ * C_DIM];
__device__ bf16 g_wqhi[NQKV * C_DIM], g_wqlo[NQKV * C_DIM];      // W_qkv^T [N][K]
__device__ bf16 g_wphi[C_DIM * C_DIM], g_wplo[C_DIM * C_DIM];    // W_proj^T [N][K]
__device__ bf16 g_qhi[H_NUM * T_SEQ * D_DIM], g_qlo[H_NUM * T_SEQ * D_DIM];   // [h][t][d], q/8
__device__ bf16 g_khi[H_NUM * T_SEQ * D_DIM], g_klo[H_NUM * T_SEQ * D_DIM];   // [h][t][d]
__device__ bf16 g_vthi[H_NUM * D_DIM * T_SEQ], g_vtlo[H_NUM * D_DIM * T_SEQ]; // [h][d][t]
__device__ bf16 g_yhi[T_SEQ * C_DIM], g_ylo[T_SEQ * C_DIM];

// ---------------- helpers ----------------
__device__ __forceinline__ uint32_t sw128(uint32_t o) { return o ^ ((o >> 3) & 0x70); }
__device__ __forceinline__ uint32_t sw32(uint32_t o) { return o ^ ((o >> 3) & 0x10); }
__device__ __forceinline__ uint32_t smem_u32(const void* p) {
    uint32_t a;
    asm("{ .reg .u64 t; cvta.to.shared.u64 t, %1; cvt.u32.u64 %0, t; }" : "=r"(a) : "l"(p));
    return a;
}
__device__ __forceinline__ void cp16(uint32_t dst, const void* src) {
    asm volatile("cp.async.cg.shared.global [%0], [%1], 16;" :: "r"(dst), "l"(src));
}
__device__ __forceinline__ void cp_commit() { asm volatile("cp.async.commit_group;"); }
template <int N>
__device__ __forceinline__ void cp_wait() {
    asm volatile("cp.async.wait_group %0;" :: "n"(N));
}
__device__ __forceinline__ void ldm4(uint32_t r[4], uint32_t addr) {
    asm volatile("ldmatrix.sync.aligned.m8n8.x4.shared.b16 {%0,%1,%2,%3}, [%4];"
                 : "=r"(r[0]), "=r"(r[1]), "=r"(r[2]), "=r"(r[3]) : "r"(addr));
}
__device__ __forceinline__ void mma16816(float* c, const uint32_t a[4], uint32_t b0,
                                         uint32_t b1) {
    asm volatile("mma.sync.aligned.m16n8k16.row.col.f32.bf16.bf16.f32 "
                 "{%0,%1,%2,%3}, {%4,%5,%6,%7}, {%8,%9}, {%0,%1,%2,%3};"
                 : "+f"(c[0]), "+f"(c[1]), "+f"(c[2]), "+f"(c[3])
                 : "r"(a[0]), "r"(a[1]), "r"(a[2]), "r"(a[3]), "r"(b0), "r"(b1));
}
__device__ __forceinline__ void split2(float v, bf16& h, bf16& l) {
    h = __float2bfloat16(v);
    l = __float2bfloat16(v - __bfloat162float(h));
}
__device__ __forceinline__ uint32_t pack2bf(bf16 a, bf16 b) {
    return (uint32_t)__bfloat16_as_ushort(a) | ((uint32_t)__bfloat16_as_ushort(b) << 16);
}
__device__ __forceinline__ void store_split_pair(bf16* hiA, bf16* loA, size_t idx, float v0,
                                                 float v1) {
    bf16 h0, l0, h1, l1;
    split2(v0, h0, l0);
    split2(v1, h1, l1);
    *(uint32_t*)(hiA + idx) = pack2bf(h0, h1);
    *(uint32_t*)(loA + idx) = pack2bf(l0, l1);
}

// ldmatrix x4 address in a [rows][64 halves] tile, 128B rows, SW128
__device__ __forceinline__ uint32_t mat_addr128(uint32_t base, int rbase, int kbase, int lane) {
    int row = rbase + (lane & 15);
    uint32_t off = row * 128 + kbase * 2 + ((lane >> 4) << 4);
    return base + sw128(off);
}
// ldmatrix x4 address in a [rows][16 halves] tile, 32B rows, sw32
__device__ __forceinline__ uint32_t mat_addr32(uint32_t base, int rbase, int lane) {
    int row = rbase + (lane & 15);
    uint32_t off = row * 32 + ((lane >> 4) << 4);
    return base + sw32(off);
}

// async tile loads
template <int ROWS, int NT>
__device__ __forceinline__ void load_tile128(uint32_t dst, const bf16* __restrict__ src,
                                             int ldK, int tid) {
#pragma unroll
    for (int i = 0; i < ROWS * 8 / NT; i++) {
        int ch = tid + i * NT;
        int row = ch >> 3, ci = ch & 7;
        cp16(dst + sw128(row * 128 + ci * 16), src + (size_t)row * ldK + ci * 8);
    }
}
template <int ROWS, int NT>
__device__ __forceinline__ void load_tile32(uint32_t dst, const bf16* __restrict__ src,
                                            int ldK, int tid) {
#pragma unroll
    for (int i = 0; i < ROWS * 2 / NT; i++) {
        int ch = tid + i * NT;
        int row = ch >> 1, ci = ch & 1;
        cp16(dst + sw32(row * 32 + ci * 16), src + (size_t)row * ldK + ci * 8);
    }
}

// ---------------- converters ----------------
__global__ void conv_x_kernel(const float* __restrict__ x) {
    int i = (blockIdx.x * blockDim.x + threadIdx.x) * 4;
    float4 v = *(const float4*)(x + i);
    float e[4] = {v.x, v.y, v.z, v.w};
#pragma unroll
    for (int j = 0; j < 4; j++) {
        bf16 h, l;
        split2(e[j], h, l);
        g_xhi[i + j] = h;
        g_xlo[i + j] = l;
    }
}
__global__ void transpose_split(const float* __restrict__ W, bf16* __restrict__ hi,
                                bf16* __restrict__ lo, int K, int N) {
    __shared__ float t[32][33];
    int n0 = blockIdx.x * 32, k0 = blockIdx.y * 32;
    int tx = threadIdx.x, ty = threadIdx.y;
#pragma unroll
    for (int i = 0; i < 4; i++) t[ty + i * 8][tx] = W[(size_t)(k0 + ty + i * 8) * N + n0 + tx];
    __syncthreads();
#pragma unroll
    for (int i = 0; i < 4; i++) {
        int n = n0 + ty + i * 8;
        bf16 h, l;
        split2(t[tx][ty + i * 8], h, l);
        hi[(size_t)n * K + k0 + tx] = h;
        lo[(size_t)n * K + k0 + tx] = l;
    }
}

// ---------------- HMMA GEMM: D[128x128] = A[128xK] . B^T, B stored [N][K] ----------
// MODE 0: scatter into g_q/g_k/g_vt (split bf16). MODE 1: fp32 out + bias.
// smem: 2 stages x (Ahi 4K | Alo 4K | Bhi 4K | Blo 4K) = 32KB static. BK=16.
template <int MODE>
__global__ __launch_bounds__(256) void mma_gemm(const bf16* __restrict__ Ahi,
                                                const bf16* __restrict__ Alo,
                                                const bf16* __restrict__ Bhi,
                                                const bf16* __restrict__ Blo,
                                                const float* __restrict__ bias,
                                                float* __restrict__ Cout, int N, int K) {
    __shared__ char smem[32768];
    uint32_t sb = smem_u32(smem);
    const int tid = threadIdx.x, lane = tid & 31, warp = tid >> 5;
    const int wm = warp >> 2, wn = warp & 3;  // 2 x 4 warp grid, 64m x 32n per warp
    const int m0 = blockIdx.y * 128, n0 = blockIdx.x * 128;

    const bf16* Ah = Ahi + (size_t)m0 * K;
    const bf16* Al = Alo + (size_t)m0 * K;
    const bf16* Bh = Bhi + (size_t)n0 * K;
    const bf16* Bl = Blo + (size_t)n0 * K;

    float acc[4][4][4];
#pragma unroll
    for (int mt = 0; mt < 4; mt++)
#pragma unroll
        for (int nt = 0; nt < 4; nt++)
#pragma unroll
            for (int e = 0; e < 4; e++) acc[mt][nt][e] = 0.0f;

    const int NS = K / 16;
    // prefetch stage 0
    {
        uint32_t b = sb;
        load_tile32<128, 256>(b, Ah, K, tid);
        load_tile32<128, 256>(b + 4096, Al, K, tid);
        load_tile32<128, 256>(b + 8192, Bh, K, tid);
        load_tile32<128, 256>(b + 12288, Bl, K, tid);
        cp_commit();
    }
#pragma unroll 1
    for (int s = 0; s < NS; s++) {
        if (s + 1 < NS) {
            uint32_t b = sb + ((s + 1) & 1) * 16384;
            const bf16* off = (const bf16*)0;
            int k0 = (s + 1) * 16;
            load_tile32<128, 256>(b, Ah + k0, K, tid);
            load_tile32<128, 256>(b + 4096, Al + k0, K, tid);
            load_tile32<128, 256>(b + 8192, Bh + k0, K, tid);
            load_tile32<128, 256>(b + 12288, Bl + k0, K, tid);
            cp_commit();
            cp_wait<1>();
        } else {
            cp_wait<0>();
        }
        __syncthreads();
        uint32_t b = sb + (s & 1) * 16384;
        uint32_t ah[4][4], al[4][4];
#pragma unroll
        for (int mt = 0; mt < 4; mt++) {
            ldm4(ah[mt], mat_addr32(b, wm * 64 + mt * 16, lane));
            ldm4(al[mt], mat_addr32(b + 4096, wm * 64 + mt * 16, lane));
        }
#pragma unroll
        for (int p = 0; p < 2; p++) {
            uint32_t bh[4], bl[4];
            ldm4(bh, mat_addr32(b + 8192, wn * 32 + p * 16, lane));
            ldm4(bl, mat_addr32(b + 12288, wn * 32 + p * 16, lane));
#pragma unroll
            for (int mt = 0; mt < 4; mt++)
#pragma unroll
                for (int q = 0; q < 2; q++) {
                    int nt = p * 2 + q;
                    mma16816(acc[mt][nt], ah[mt], bh[q], bh[2 + q]);
                    mma16816(acc[mt][nt], ah[mt], bl[q], bl[2 + q]);
                    mma16816(acc[mt][nt], al[mt], bh[q], bh[2 + q]);
                }
        }
        __syncthreads();
    }

    // epilogue: acc[mt][nt]: rows r0,r0+8 ; cols c0,c0+1
#pragma unroll
    for (int mt = 0; mt < 4; mt++)
#pragma unroll
        for (int nt = 0; nt < 4; nt++) {
            int r0 = m0 + wm * 64 + mt * 16 + (lane >> 2);
            int c0 = n0 + wn * 32 + nt * 8 + 2 * (lane & 3);
            float bv0 = bias[c0], bv1 = bias[c0 + 1];
            float v0 = acc[mt][nt][0] + bv0, v1 = acc[mt][nt][1] + bv1;
            float v2 = acc[mt][nt][2] + bv0, v3 = acc[mt][nt][3] + bv1;
            if (MODE == 1) {
                float2 p0 = make_float2(v0, v1), p1 = make_float2(v2, v3);
                *(float2*)&Cout[(size_t)r0 * N + c0] = p0;
                *(float2*)&Cout[(size_t)(r0 + 8) * N + c0] = p1;
            } else {
                int which = n0 / C_DIM;
                int cm = c0 % C_DIM;
                int h = cm >> 6, d = cm & 63;
                if (which == 0) {
                    store_split_pair(g_qhi, g_qlo, ((size_t)h * T_SEQ + r0) * D_DIM + d,
                                     v0 * 0.125f, v1 * 0.125f);
                    store_split_pair(g_qhi, g_qlo, ((size_t)h * T_SEQ + r0 + 8) * D_DIM + d,
                                     v2 * 0.125f, v3 * 0.125f);
                } else if (which == 1) {
                    store_split_pair(g_khi, g_klo, ((size_t)h * T_SEQ + r0) * D_DIM + d, v0, v1);
                    store_split_pair(g_khi, g_klo, ((size_t)h * T_SEQ + r0 + 8) * D_DIM + d, v2,
                                     v3);
                } else {
                    size_t b0 = ((size_t)h * D_DIM + d) * T_SEQ;
                    size_t b1 = ((size_t)h * D_DIM + d + 1) * T_SEQ;
                    bf16 hh, ll;
                    split2(v0, hh, ll); g_vthi[b0 + r0] = hh; g_vtlo[b0 + r0] = ll;
                    split2(v1, hh, ll); g_vthi[b1 + r0] = hh; g_vtlo[b1 + r0] = ll;
                    split2(v2, hh, ll); g_vthi[b0 + r0 + 8] = hh; g_vtlo[b0 + r0 + 8] = ll;
                    split2(v3, hh, ll); g_vthi[b1 + r0 + 8] = hh; g_vtlo[b1 + r0 + 8] = ll;
                }
            }
        }
}

// ---------------- flash attention on HMMA ----------------
// Block: 128 threads = 4 warps, 64 q-rows (warp w owns rows w*16..+15), kv tiles of 64.
// smem: Khi 8K | Klo 8K | Vhi 8K | Vlo 8K (K area doubles as Q staging).
__global__ __launch_bounds__(128) void flash_mma() {
    __shared__ char smem[32768];
    uint32_t sb = smem_u32(smem);
    const int tid = threadIdx.x, lane = tid & 31, w = tid >> 5;
    const int h = blockIdx.y;
    const int r0l = lane >> 2;        // warp-local row (and +8)
    const int c0l = 2 * (lane & 3);   // col pair base within n8 tile

#pragma unroll 1
    for (int pass = 0; pass < 2; pass++) {
        const int qb = pass ? 63 - (int)blockIdx.x : (int)blockIdx.x;
        const int qm0 = qb * 64;

        __syncthreads();
        load_tile128<64, 128>(sb, g_qhi + ((size_t)h * T_SEQ + qm0) * D_DIM, D_DIM, tid);
        load_tile128<64, 128>(sb + 8192, g_qlo + ((size_t)h * T_SEQ + qm0) * D_DIM, D_DIM, tid);
        cp_commit();
        cp_wait<0>();
        __syncthreads();

        uint32_t qh[4][4], ql[4][4];
#pragma unroll
        for (int kt = 0; kt < 4; kt++) {
            ldm4(qh[kt], mat_addr128(sb, w * 16, kt * 16, lane));
            ldm4(ql[kt], mat_addr128(sb + 8192, w * 16, kt * 16, lane));
        }

        float mi0 = -1e30f, mi1 = -1e30f, li0 = 0.0f, li1 = 0.0f;
        float O[8][4];
#pragma unroll
        for (int nt = 0; nt < 8; nt++)
#pragma unroll
            for (int e = 0; e < 4; e++) O[nt][e] = 0.0f;

        const int nkv = qb + 1;
#pragma unroll 1
        for (int j = 0; j < nkv; j++) {
            const int kv0 = j * 64;
            __syncthreads();
            load_tile128<64, 128>(sb, g_khi + ((size_t)h * T_SEQ + kv0) * D_DIM, D_DIM, tid);
            load_tile128<64, 128>(sb + 8192, g_klo + ((size_t)h * T_SEQ + kv0) * D_DIM, D_DIM, tid);
            load_tile128<64, 128>(sb + 16384, g_vthi + (size_t)h * D_DIM * T_SEQ + kv0, T_SEQ, tid);
            load_tile128<64, 128>(sb + 24576, g_vtlo + (size_t)h * D_DIM * T_SEQ + kv0, T_SEQ, tid);
            cp_commit();
            cp_wait<0>();
            __syncthreads();

            // S = Q . K^T
            float S[8][4];
#pragma unroll
            for (int nt = 0; nt < 8; nt++)
#pragma unroll
                for (int e = 0; e < 4; e++) S[nt][e] = 0.0f;
#pragma unroll
            for (int p = 0; p < 4; p++)
#pragma unroll
                for (int kt = 0; kt < 4; kt++) {
                    uint32_t kh[4], kl[4];
                    ldm4(kh, mat_addr128(sb, p * 16, kt * 16, lane));
                    ldm4(kl, mat_addr128(sb + 8192, p * 16, kt * 16, lane));
#pragma unroll
                    for (int q = 0; q < 2; q++) {
                        int nt = 2 * p + q;
                        mma16816(S[nt], qh[kt], kh[q], kh[2 + q]);
                        mma16816(S[nt], qh[kt], kl[q], kl[2 + q]);
                        mma16816(S[nt], ql[kt], kh[q], kh[2 + q]);
                    }
                }

            if (j == qb) {  // diagonal: causal mask
                int rg0 = qm0 + w * 16 + r0l, rg1 = rg0 + 8;
#pragma unroll
                for (int nt = 0; nt < 8; nt++) {
                    int cg = kv0 + nt * 8 + c0l;
                    if (cg > rg0) S[nt][0] = -1e30f;
                    if (cg + 1 > rg0) S[nt][1] = -1e30f;
                    if (cg > rg1) S[nt][2] = -1e30f;
                    if (cg + 1 > rg1) S[nt][3] = -1e30f;
                }
            }

            // online softmax (rows r0l, r0l+8; reduce over lanes xor 1,2)
            float rm0 = -1e30f, rm1 = -1e30f;
#pragma unroll
            for (int nt = 0; nt < 8; nt++) {
                rm0 = fmaxf(rm0, fmaxf(S[nt][0], S[nt][1]));
                rm1 = fmaxf(rm1, fmaxf(S[nt][2], S[nt][3]));
            }
            rm0 = fmaxf(rm0, __shfl_xor_sync(0xffffffffu, rm0, 1));
            rm0 = fmaxf(rm0, __shfl_xor_sync(0xffffffffu, rm0, 2));
            rm1 = fmaxf(rm1, __shfl_xor_sync(0xffffffffu, rm1, 1));
            rm1 = fmaxf(rm1, __shfl_xor_sync(0xffffffffu, rm1, 2));
            float mn0 = fmaxf(mi0, rm0), mn1 = fmaxf(mi1, rm1);
            float al0 = __expf(mi0 - mn0), al1 = __expf(mi1 - mn1);
            mi0 = mn0;
            mi1 = mn1;
            float rs0 = 0.0f, rs1 = 0.0f;
#pragma unroll
            for (int nt = 0; nt < 8; nt++) {
                S[nt][0] = __expf(S[nt][0] - mn0);
                S[nt][1] = __expf(S[nt][1] - mn0);
                S[nt][2] = __expf(S[nt][2] - mn1);
                S[nt][3] = __expf(S[nt][3] - mn1);
                rs0 += S[nt][0] + S[nt][1];
                rs1 += S[nt][2] + S[nt][3];
            }
            rs0 += __shfl_xor_sync(0xffffffffu, rs0, 1);
            rs0 += __shfl_xor_sync(0xffffffffu, rs0, 2);
            rs1 += __shfl_xor_sync(0xffffffffu, rs1, 1);
            rs1 += __shfl_xor_sync(0xffffffffu, rs1, 2);
            li0 = li0 * al0 + rs0;
            li1 = li1 * al1 + rs1;
#pragma unroll
            for (int nt = 0; nt < 8; nt++) {
                O[nt][0] *= al0;
                O[nt][1] *= al0;
                O[nt][2] *= al1;
                O[nt][3] *= al1;
            }

            // P frags in registers (S C-frag layout == PV A-frag layout)
            uint32_t ph[4][4], pl[4][4];
#pragma unroll
            for (int kt = 0; kt < 4; kt++) {
                bf16 h0, l0, h1, l1;
                split2(S[2 * kt][0], h0, l0);
                split2(S[2 * kt][1], h1, l1);
                ph[kt][0] = pack2bf(h0, h1);
                pl[kt][0] = pack2bf(l0, l1);
                split2(S[2 * kt][2], h0, l0);
                split2(S[2 * kt][3], h1, l1);
                ph[kt][1] = pack2bf(h0, h1);
                pl[kt][1] = pack2bf(l0, l1);
                split2(S[2 * kt + 1][0], h0, l0);
                split2(S[2 * kt + 1][1], h1, l1);
                ph[kt][2] = pack2bf(h0, h1);
                pl[kt][2] = pack2bf(l0, l1);
                split2(S[2 * kt + 1][2], h0, l0);
                split2(S[2 * kt + 1][3], h1, l1);
                ph[kt][3] = pack2bf(h0, h1);
                pl[kt][3] = pack2bf(l0, l1);
            }

            // O += P . V   (V smem is [d][t] k-contiguous)
#pragma unroll
            for (int p = 0; p < 4; p++)
#pragma unroll
                for (int kt = 0; kt < 4; kt++) {
                    uint32_t vh[4], vl[4];
                    ldm4(vh, mat_addr128(sb + 16384, p * 16, kt * 16, lane));
                    ldm4(vl, mat_addr128(sb + 24576, p * 16, kt * 16, lane));
#pragma unroll
                    for (int q = 0; q < 2; q++) {
                        int nt = 2 * p + q;
                        mma16816(O[nt], ph[kt], vh[q], vh[2 + q]);
                        mma16816(O[nt], ph[kt], vl[q], vl[2 + q]);
                        mma16816(O[nt], pl[kt], vh[q], vh[2 + q]);
                    }
                }
        }

        // finalize: write y (split bf16), y layout [t][h*64+d]
        float inv0 = 1.0f / li0, inv1 = 1.0f / li1;
        int rg0 = qm0 + w * 16 + r0l;
#pragma unroll
        for (int nt = 0; nt < 8; nt++) {
            int d = nt * 8 + c0l;
            size_t i0 = (size_t)rg0 * C_DIM + h * 64 + d;
            size_t i1 = (size_t)(rg0 + 8) * C_DIM + h * 64 + d;
            store_split_pair(g_yhi, g_ylo, i0, O[nt][0] * inv0, O[nt][1] * inv0);
            store_split_pair(g_yhi, g_ylo, i1, O[nt][2] * inv1, O[nt][3] * inv1);
        }
    }
}

// ---------------- launch ----------------
extern "C" void kernel_launch(void* const* d_in, const int* in_sizes, int n_in,
                              void* d_out, int out_size) {
    const float* x = (const float*)d_in[0];
    const float* Wqkv = (const float*)d_in[2];
    const float* bqkv = (const float*)d_in[3];
    const float* Wproj = (const float*)d_in[4];
    const float* bproj = (const float*)d_in[5];
    float* out = (float*)d_out;

    void *xhi, *xlo, *wqhi, *wqlo, *wphi, *wplo, *yhi, *ylo;
    cudaGetSymbolAddress(&xhi, g_xhi);
    cudaGetSymbolAddress(&xlo, g_xlo);
    cudaGetSymbolAddress(&wqhi, g_wqhi);
    cudaGetSymbolAddress(&wqlo, g_wqlo);
    cudaGetSymbolAddress(&wphi, g_wphi);
    cudaGetSymbolAddress(&wplo, g_wplo);
    cudaGetSymbolAddress(&yhi, g_yhi);
    cudaGetSymbolAddress(&ylo, g_ylo);

    conv_x_kernel<<<3072, 256>>>(x);
    transpose_split<<<dim3(72, 24), dim3(32, 8)>>>(Wqkv, (bf16*)wqhi, (bf16*)wqlo, C_DIM, NQKV);
    transpose_split<<<dim3(24, 24), dim3(32, 8)>>>(Wproj, (bf16*)wphi, (bf16*)wplo, C_DIM, C_DIM);
    mma_gemm<0><<<dim3(18, 32), 256>>>((const bf16*)xhi, (const bf16*)xlo, (const bf16*)wqhi,
                                       (const bf16*)wqlo, bqkv, nullptr, NQKV, C_DIM);
    flash_mma<<<dim3(32, H_NUM), 128>>>();
    mma_gemm<1><<<dim3(6, 32), 256>>>((const bf16*)yhi, (const bf16*)ylo, (const bf16*)wphi,
                                      (const bf16*)wplo, bproj, out, C_DIM, C_DIM);
}

// round 10
// speedup vs baseline: 2.3171x; 1.0396x over previous
#include <cuda_runtime.h>
#include <cuda_bf16.h>
#include <cstdint>

typedef __nv_bfloat16 bf16;

#define T_SEQ 4096
#define C_DIM 768
#define H_NUM 12
#define D_DIM 64
#define NQKV  2304

// ---------------- scratch (__device__ globals; no allocation) ----------------
__device__ bf16 g_xhi[T_SEQ * C_DIM], g_xlo[T_SEQ * C_DIM];
__device__ bf16 g_wqhi[NQKV * C_DIM], g_wqlo[NQKV * C_DIM];      // W_qkv^T [N][K]
__device__ bf16 g_wphi[C_DIM * C_DIM], g_wplo[C_DIM * C_DIM];    // W_proj^T [N][K]
__device__ bf16 g_qhi[H_NUM * T_SEQ * D_DIM], g_qlo[H_NUM * T_SEQ * D_DIM];   // [h][t][d], q/8
__device__ bf16 g_khi[H_NUM * T_SEQ * D_DIM], g_klo[H_NUM * T_SEQ * D_DIM];   // [h][t][d]
__device__ bf16 g_vthi[H_NUM * D_DIM * T_SEQ], g_vtlo[H_NUM * D_DIM * T_SEQ]; // [h][d][t]
__device__ bf16 g_yhi[T_SEQ * C_DIM], g_ylo[T_SEQ * C_DIM];

// ---------------- helpers ----------------
__device__ __forceinline__ uint32_t sw128(uint32_t o) { return o ^ ((o >> 3) & 0x70); }
__device__ __forceinline__ uint32_t sw32(uint32_t o) { return o ^ ((o >> 3) & 0x10); }
__device__ __forceinline__ uint32_t smem_u32(const void* p) {
    uint32_t a;
    asm("{ .reg .u64 t; cvta.to.shared.u64 t, %1; cvt.u32.u64 %0, t; }" : "=r"(a) : "l"(p));
    return a;
}
__device__ __forceinline__ void cp16(uint32_t dst, const void* src) {
    asm volatile("cp.async.cg.shared.global [%0], [%1], 16;" :: "r"(dst), "l"(src));
}
__device__ __forceinline__ void cp_commit() { asm volatile("cp.async.commit_group;"); }
template <int N>
__device__ __forceinline__ void cp_wait() {
    asm volatile("cp.async.wait_group %0;" :: "n"(N));
}
__device__ __forceinline__ void ldm4(uint32_t r[4], uint32_t addr) {
    asm volatile("ldmatrix.sync.aligned.m8n8.x4.shared.b16 {%0,%1,%2,%3}, [%4];"
                 : "=r"(r[0]), "=r"(r[1]), "=r"(r[2]), "=r"(r[3]) : "r"(addr));
}
__device__ __forceinline__ void mma16816(float* c, const uint32_t a[4], uint32_t b0,
                                         uint32_t b1) {
    asm volatile("mma.sync.aligned.m16n8k16.row.col.f32.bf16.bf16.f32 "
                 "{%0,%1,%2,%3}, {%4,%5,%6,%7}, {%8,%9}, {%0,%1,%2,%3};"
                 : "+f"(c[0]), "+f"(c[1]), "+f"(c[2]), "+f"(c[3])
                 : "r"(a[0]), "r"(a[1]), "r"(a[2]), "r"(a[3]), "r"(b0), "r"(b1));
}
__device__ __forceinline__ void split2(float v, bf16& h, bf16& l) {
    h = __float2bfloat16(v);
    l = __float2bfloat16(v - __bfloat162float(h));
}
__device__ __forceinline__ uint32_t pack2bf(bf16 a, bf16 b) {
    return (uint32_t)__bfloat16_as_ushort(a) | ((uint32_t)__bfloat16_as_ushort(b) << 16);
}
__device__ __forceinline__ void store_split_pair(bf16* hiA, bf16* loA, size_t idx, float v0,
                                                 float v1) {
    bf16 h0, l0, h1, l1;
    split2(v0, h0, l0);
    split2(v1, h1, l1);
    *(uint32_t*)(hiA + idx) = pack2bf(h0, h1);
    *(uint32_t*)(loA + idx) = pack2bf(l0, l1);
}

// ldmatrix x4 address in a [rows][64 halves] tile, 128B rows, SW128
__device__ __forceinline__ uint32_t mat_addr128(uint32_t base, int rbase, int kbase, int lane) {
    int row = rbase + (lane & 15);
    uint32_t off = row * 128 + kbase * 2 + ((lane >> 4) << 4);
    return base + sw128(off);
}
// ldmatrix x4 address in a [rows][16 halves] tile, 32B rows, sw32
__device__ __forceinline__ uint32_t mat_addr32(uint32_t base, int rbase, int lane) {
    int row = rbase + (lane & 15);
    uint32_t off = row * 32 + ((lane >> 4) << 4);
    return base + sw32(off);
}

// async tile loads
template <int ROWS, int NT>
__device__ __forceinline__ void load_tile128(uint32_t dst, const bf16* __restrict__ src,
                                             int ldK, int tid) {
#pragma unroll
    for (int i = 0; i < ROWS * 8 / NT; i++) {
        int ch = tid + i * NT;
        int row = ch >> 3, ci = ch & 7;
        cp16(dst + sw128(row * 128 + ci * 16), src + (size_t)row * ldK + ci * 8);
    }
}
template <int ROWS, int NT>
__device__ __forceinline__ void load_tile32(uint32_t dst, const bf16* __restrict__ src,
                                            int ldK, int tid) {
#pragma unroll
    for (int i = 0; i < ROWS * 2 / NT; i++) {
        int ch = tid + i * NT;
        int row = ch >> 1, ci = ch & 1;
        cp16(dst + sw32(row * 32 + ci * 16), src + (size_t)row * ldK + ci * 8);
    }
}

// ---------------- converters ----------------
__global__ void conv_x_kernel(const float* __restrict__ x) {
    int i = (blockIdx.x * blockDim.x + threadIdx.x) * 4;
    float4 v = *(const float4*)(x + i);
    float e[4] = {v.x, v.y, v.z, v.w};
#pragma unroll
    for (int j = 0; j < 4; j++) {
        bf16 h, l;
        split2(e[j], h, l);
        g_xhi[i + j] = h;
        g_xlo[i + j] = l;
    }
}
__global__ void transpose_split(const float* __restrict__ W, bf16* __restrict__ hi,
                                bf16* __restrict__ lo, int K, int N) {
    __shared__ float t[32][33];
    int n0 = blockIdx.x * 32, k0 = blockIdx.y * 32;
    int tx = threadIdx.x, ty = threadIdx.y;
#pragma unroll
    for (int i = 0; i < 4; i++) t[ty + i * 8][tx] = W[(size_t)(k0 + ty + i * 8) * N + n0 + tx];
    __syncthreads();
#pragma unroll
    for (int i = 0; i < 4; i++) {
        int n = n0 + ty + i * 8;
        bf16 h, l;
        split2(t[tx][ty + i * 8], h, l);
        hi[(size_t)n * K + k0 + tx] = h;
        lo[(size_t)n * K + k0 + tx] = l;
    }
}

// ---------------- HMMA GEMM: D[128x128] = A[128xK] . B^T, B stored [N][K] ----------
// 3-stage cp.async pipeline, BK=16. smem: 3 x (Ahi|Alo|Bhi|Blo 4K each) = 48KB.
template <int MODE>
__global__ __launch_bounds__(256) void mma_gemm(const bf16* __restrict__ Ahi,
                                                const bf16* __restrict__ Alo,
                                                const bf16* __restrict__ Bhi,
                                                const bf16* __restrict__ Blo,
                                                const float* __restrict__ bias,
                                                float* __restrict__ Cout, int N, int K) {
    __shared__ char smem[49152];
    uint32_t sb = smem_u32(smem);
    const int tid = threadIdx.x, lane = tid & 31, warp = tid >> 5;
    const int wm = warp >> 2, wn = warp & 3;  // 2 x 4 warp grid, 64m x 32n per warp
    const int m0 = blockIdx.y * 128, n0 = blockIdx.x * 128;

    const bf16* Ah = Ahi + (size_t)m0 * K;
    const bf16* Al = Alo + (size_t)m0 * K;
    const bf16* Bh = Bhi + (size_t)n0 * K;
    const bf16* Bl = Blo + (size_t)n0 * K;

    float acc[4][4][4];
#pragma unroll
    for (int mt = 0; mt < 4; mt++)
#pragma unroll
        for (int nt = 0; nt < 4; nt++)
#pragma unroll
            for (int e = 0; e < 4; e++) acc[mt][nt][e] = 0.0f;

    const int NS = K / 16;
    // prefetch stages 0,1
#pragma unroll
    for (int p = 0; p < 2; p++) {
        uint32_t b = sb + p * 16384;
        int k0 = p * 16;
        load_tile32<128, 256>(b, Ah + k0, K, tid);
        load_tile32<128, 256>(b + 4096, Al + k0, K, tid);
        load_tile32<128, 256>(b + 8192, Bh + k0, K, tid);
        load_tile32<128, 256>(b + 12288, Bl + k0, K, tid);
        cp_commit();
    }
#pragma unroll 1
    for (int s = 0; s < NS; s++) {
        if (s + 2 < NS) {
            uint32_t b = sb + ((s + 2) % 3) * 16384;
            int k0 = (s + 2) * 16;
            load_tile32<128, 256>(b, Ah + k0, K, tid);
            load_tile32<128, 256>(b + 4096, Al + k0, K, tid);
            load_tile32<128, 256>(b + 8192, Bh + k0, K, tid);
            load_tile32<128, 256>(b + 12288, Bl + k0, K, tid);
            cp_commit();
            cp_wait<2>();
        } else if (s + 1 < NS) {
            cp_wait<1>();
        } else {
            cp_wait<0>();
        }
        __syncthreads();
        uint32_t b = sb + (s % 3) * 16384;
        uint32_t ah[4][4], al[4][4];
#pragma unroll
        for (int mt = 0; mt < 4; mt++) {
            ldm4(ah[mt], mat_addr32(b, wm * 64 + mt * 16, lane));
            ldm4(al[mt], mat_addr32(b + 4096, wm * 64 + mt * 16, lane));
        }
#pragma unroll
        for (int p = 0; p < 2; p++) {
            uint32_t bh[4], bl[4];
            ldm4(bh, mat_addr32(b + 8192, wn * 32 + p * 16, lane));
            ldm4(bl, mat_addr32(b + 12288, wn * 32 + p * 16, lane));
#pragma unroll
            for (int mt = 0; mt < 4; mt++)
#pragma unroll
                for (int q = 0; q < 2; q++) {
                    int nt = p * 2 + q;
                    mma16816(acc[mt][nt], ah[mt], bh[q], bh[2 + q]);
                    mma16816(acc[mt][nt], ah[mt], bl[q], bl[2 + q]);
                    mma16816(acc[mt][nt], al[mt], bh[q], bh[2 + q]);
                }
        }
        __syncthreads();
    }

    // epilogue: acc[mt][nt]: rows r0,r0+8 ; cols c0,c0+1
#pragma unroll
    for (int mt = 0; mt < 4; mt++)
#pragma unroll
        for (int nt = 0; nt < 4; nt++) {
            int r0 = m0 + wm * 64 + mt * 16 + (lane >> 2);
            int c0 = n0 + wn * 32 + nt * 8 + 2 * (lane & 3);
            float bv0 = bias[c0], bv1 = bias[c0 + 1];
            float v0 = acc[mt][nt][0] + bv0, v1 = acc[mt][nt][1] + bv1;
            float v2 = acc[mt][nt][2] + bv0, v3 = acc[mt][nt][3] + bv1;
            if (MODE == 1) {
                float2 p0 = make_float2(v0, v1), p1 = make_float2(v2, v3);
                *(float2*)&Cout[(size_t)r0 * N + c0] = p0;
                *(float2*)&Cout[(size_t)(r0 + 8) * N + c0] = p1;
            } else {
                int which = n0 / C_DIM;
                int cm = c0 % C_DIM;
                int h = cm >> 6, d = cm & 63;
                if (which == 0) {
                    store_split_pair(g_qhi, g_qlo, ((size_t)h * T_SEQ + r0) * D_DIM + d,
                                     v0 * 0.125f, v1 * 0.125f);
                    store_split_pair(g_qhi, g_qlo, ((size_t)h * T_SEQ + r0 + 8) * D_DIM + d,
                                     v2 * 0.125f, v3 * 0.125f);
                } else if (which == 1) {
                    store_split_pair(g_khi, g_klo, ((size_t)h * T_SEQ + r0) * D_DIM + d, v0, v1);
                    store_split_pair(g_khi, g_klo, ((size_t)h * T_SEQ + r0 + 8) * D_DIM + d, v2,
                                     v3);
                } else {
                    size_t b0 = ((size_t)h * D_DIM + d) * T_SEQ;
                    size_t b1 = ((size_t)h * D_DIM + d + 1) * T_SEQ;
                    bf16 hh, ll;
                    split2(v0, hh, ll); g_vthi[b0 + r0] = hh; g_vtlo[b0 + r0] = ll;
                    split2(v1, hh, ll); g_vthi[b1 + r0] = hh; g_vtlo[b1 + r0] = ll;
                    split2(v2, hh, ll); g_vthi[b0 + r0 + 8] = hh; g_vtlo[b0 + r0 + 8] = ll;
                    split2(v3, hh, ll); g_vthi[b1 + r0 + 8] = hh; g_vtlo[b1 + r0 + 8] = ll;
                }
            }
        }
}

// ---------------- flash attention on HMMA (pipelined K/V loads) ----------------
// Block: 128 threads = 4 warps, 64 q-rows (warp w owns rows w*16..+15), kv tiles of 64.
// smem: Khi 8K | Klo 8K | Vhi 8K | Vlo 8K (K area doubles as Q staging).
// Pipeline: V_j load overlaps S_j compute; K_{j+1} issue overlaps softmax+PV_j;
//           V_{j+1} issue at iter end overlaps S_{j+1}.
__global__ __launch_bounds__(128) void flash_mma() {
    __shared__ char smem[32768];
    uint32_t sb = smem_u32(smem);
    const int tid = threadIdx.x, lane = tid & 31, w = tid >> 5;
    const int h = blockIdx.y;
    const int r0l = lane >> 2;
    const int c0l = 2 * (lane & 3);

    const bf16* khB = g_khi + (size_t)h * T_SEQ * D_DIM;
    const bf16* klB = g_klo + (size_t)h * T_SEQ * D_DIM;
    const bf16* vhB = g_vthi + (size_t)h * D_DIM * T_SEQ;
    const bf16* vlB = g_vtlo + (size_t)h * D_DIM * T_SEQ;

#pragma unroll 1
    for (int pass = 0; pass < 2; pass++) {
        const int qb = pass ? 63 - (int)blockIdx.x : (int)blockIdx.x;
        const int qm0 = qb * 64;

        __syncthreads();
        load_tile128<64, 128>(sb, g_qhi + ((size_t)h * T_SEQ + qm0) * D_DIM, D_DIM, tid);
        load_tile128<64, 128>(sb + 8192, g_qlo + ((size_t)h * T_SEQ + qm0) * D_DIM, D_DIM, tid);
        cp_commit();
        cp_wait<0>();
        __syncthreads();

        uint32_t qh[4][4], ql[4][4];
#pragma unroll
        for (int kt = 0; kt < 4; kt++) {
            ldm4(qh[kt], mat_addr128(sb, w * 16, kt * 16, lane));
            ldm4(ql[kt], mat_addr128(sb + 8192, w * 16, kt * 16, lane));
        }
        __syncthreads();  // all warps done reading Q staging before K0 overwrites

        // issue K0 then V0 as separate groups
        load_tile128<64, 128>(sb, khB, D_DIM, tid);
        load_tile128<64, 128>(sb + 8192, klB, D_DIM, tid);
        cp_commit();
        load_tile128<64, 128>(sb + 16384, vhB, T_SEQ, tid);
        load_tile128<64, 128>(sb + 24576, vlB, T_SEQ, tid);
        cp_commit();

        float mi0 = -1e30f, mi1 = -1e30f, li0 = 0.0f, li1 = 0.0f;
        float O[8][4];
#pragma unroll
        for (int nt = 0; nt < 8; nt++)
#pragma unroll
            for (int e = 0; e < 4; e++) O[nt][e] = 0.0f;

        const int nkv = qb + 1;
#pragma unroll 1
        for (int j = 0; j < nkv; j++) {
            const int kv0 = j * 64;
            cp_wait<1>();  // K_j complete (V_j may still be in flight)
            __syncthreads();

            // S = Q . K^T
            float S[8][4];
#pragma unroll
            for (int nt = 0; nt < 8; nt++)
#pragma unroll
                for (int e = 0; e < 4; e++) S[nt][e] = 0.0f;
#pragma unroll
            for (int p = 0; p < 4; p++)
#pragma unroll
                for (int kt = 0; kt < 4; kt++) {
                    uint32_t kh[4], kl[4];
                    ldm4(kh, mat_addr128(sb, p * 16, kt * 16, lane));
                    ldm4(kl, mat_addr128(sb + 8192, p * 16, kt * 16, lane));
#pragma unroll
                    for (int q = 0; q < 2; q++) {
                        int nt = 2 * p + q;
                        mma16816(S[nt], qh[kt], kh[q], kh[2 + q]);
                        mma16816(S[nt], qh[kt], kl[q], kl[2 + q]);
                        mma16816(S[nt], ql[kt], kh[q], kh[2 + q]);
                    }
                }

            cp_wait<0>();     // V_j complete
            __syncthreads();  // all warps done reading K_j

            // prefetch K_{j+1} over softmax + PV compute
            if (j + 1 < nkv) {
                load_tile128<64, 128>(sb, khB + (size_t)(kv0 + 64) * D_DIM, D_DIM, tid);
                load_tile128<64, 128>(sb + 8192, klB + (size_t)(kv0 + 64) * D_DIM, D_DIM, tid);
                cp_commit();
            }

            if (j == qb) {  // diagonal: causal mask
                int rg0 = qm0 + w * 16 + r0l, rg1 = rg0 + 8;
#pragma unroll
                for (int nt = 0; nt < 8; nt++) {
                    int cg = kv0 + nt * 8 + c0l;
                    if (cg > rg0) S[nt][0] = -1e30f;
                    if (cg + 1 > rg0) S[nt][1] = -1e30f;
                    if (cg > rg1) S[nt][2] = -1e30f;
                    if (cg + 1 > rg1) S[nt][3] = -1e30f;
                }
            }

            // online softmax (rows r0l, r0l+8; reduce over lanes xor 1,2)
            float rm0 = -1e30f, rm1 = -1e30f;
#pragma unroll
            for (int nt = 0; nt < 8; nt++) {
                rm0 = fmaxf(rm0, fmaxf(S[nt][0], S[nt][1]));
                rm1 = fmaxf(rm1, fmaxf(S[nt][2], S[nt][3]));
            }
            rm0 = fmaxf(rm0, __shfl_xor_sync(0xffffffffu, rm0, 1));
            rm0 = fmaxf(rm0, __shfl_xor_sync(0xffffffffu, rm0, 2));
            rm1 = fmaxf(rm1, __shfl_xor_sync(0xffffffffu, rm1, 1));
            rm1 = fmaxf(rm1, __shfl_xor_sync(0xffffffffu, rm1, 2));
            float mn0 = fmaxf(mi0, rm0), mn1 = fmaxf(mi1, rm1);
            float al0 = __expf(mi0 - mn0), al1 = __expf(mi1 - mn1);
            mi0 = mn0;
            mi1 = mn1;
            float rs0 = 0.0f, rs1 = 0.0f;
#pragma unroll
            for (int nt = 0; nt < 8; nt++) {
                S[nt][0] = __expf(S[nt][0] - mn0);
                S[nt][1] = __expf(S[nt][1] - mn0);
                S[nt][2] = __expf(S[nt][2] - mn1);
                S[nt][3] = __expf(S[nt][3] - mn1);
                rs0 += S[nt][0] + S[nt][1];
                rs1 += S[nt][2] + S[nt][3];
            }
            rs0 += __shfl_xor_sync(0xffffffffu, rs0, 1);
            rs0 += __shfl_xor_sync(0xffffffffu, rs0, 2);
            rs1 += __shfl_xor_sync(0xffffffffu, rs1, 1);
            rs1 += __shfl_xor_sync(0xffffffffu, rs1, 2);
            li0 = li0 * al0 + rs0;
            li1 = li1 * al1 + rs1;
#pragma unroll
            for (int nt = 0; nt < 8; nt++) {
                O[nt][0] *= al0;
                O[nt][1] *= al0;
                O[nt][2] *= al1;
                O[nt][3] *= al1;
            }

            // P frags in registers (S C-frag layout == PV A-frag layout)
            uint32_t ph[4][4], pl[4][4];
#pragma unroll
            for (int kt = 0; kt < 4; kt++) {
                bf16 h0, l0, h1, l1;
                split2(S[2 * kt][0], h0, l0);
                split2(S[2 * kt][1], h1, l1);
                ph[kt][0] = pack2bf(h0, h1);
                pl[kt][0] = pack2bf(l0, l1);
                split2(S[2 * kt][2], h0, l0);
                split2(S[2 * kt][3], h1, l1);
                ph[kt][1] = pack2bf(h0, h1);
                pl[kt][1] = pack2bf(l0, l1);
                split2(S[2 * kt + 1][0], h0, l0);
                split2(S[2 * kt + 1][1], h1, l1);
                ph[kt][2] = pack2bf(h0, h1);
                pl[kt][2] = pack2bf(l0, l1);
                split2(S[2 * kt + 1][2], h0, l0);
                split2(S[2 * kt + 1][3], h1, l1);
                ph[kt][3] = pack2bf(h0, h1);
                pl[kt][3] = pack2bf(l0, l1);
            }

            // O += P . V   (V smem is [d][t] k-contiguous)
#pragma unroll
            for (int p = 0; p < 4; p++)
#pragma unroll
                for (int kt = 0; kt < 4; kt++) {
                    uint32_t vh[4], vl[4];
                    ldm4(vh, mat_addr128(sb + 16384, p * 16, kt * 16, lane));
                    ldm4(vl, mat_addr128(sb + 24576, p * 16, kt * 16, lane));
#pragma unroll
                    for (int q = 0; q < 2; q++) {
                        int nt = 2 * p + q;
                        mma16816(O[nt], ph[kt], vh[q], vh[2 + q]);
                        mma16816(O[nt], ph[kt], vl[q], vl[2 + q]);
                        mma16816(O[nt], pl[kt], vh[q], vh[2 + q]);
                    }
                }

            __syncthreads();  // all warps done reading V_j
            if (j + 1 < nkv) {
                load_tile128<64, 128>(sb + 16384, vhB + kv0 + 64, T_SEQ, tid);
                load_tile128<64, 128>(sb + 24576, vlB + kv0 + 64, T_SEQ, tid);
                cp_commit();
            }
        }

        // finalize: write y (split bf16), y layout [t][h*64+d]
        float inv0 = 1.0f / li0, inv1 = 1.0f / li1;
        int rg0 = qm0 + w * 16 + r0l;
#pragma unroll
        for (int nt = 0; nt < 8; nt++) {
            int d = nt * 8 + c0l;
            size_t i0 = (size_t)rg0 * C_DIM + h * 64 + d;
            size_t i1 = (size_t)(rg0 + 8) * C_DIM + h * 64 + d;
            store_split_pair(g_yhi, g_ylo, i0, O[nt][0] * inv0, O[nt][1] * inv0);
            store_split_pair(g_yhi, g_ylo, i1, O[nt][2] * inv1, O[nt][3] * inv1);
        }
    }
}

// ---------------- launch ----------------
extern "C" void kernel_launch(void* const* d_in, const int* in_sizes, int n_in,
                              void* d_out, int out_size) {
    const float* x = (const float*)d_in[0];
    const float* Wqkv = (const float*)d_in[2];
    const float* bqkv = (const float*)d_in[3];
    const float* Wproj = (const float*)d_in[4];
    const float* bproj = (const float*)d_in[5];
    float* out = (float*)d_out;

    void *xhi, *xlo, *wqhi, *wqlo, *wphi, *wplo, *yhi, *ylo;
    cudaGetSymbolAddress(&xhi, g_xhi);
    cudaGetSymbolAddress(&xlo, g_xlo);
    cudaGetSymbolAddress(&wqhi, g_wqhi);
    cudaGetSymbolAddress(&wqlo, g_wqlo);
    cudaGetSymbolAddress(&wphi, g_wphi);
    cudaGetSymbolAddress(&wplo, g_wplo);
    cudaGetSymbolAddress(&yhi, g_yhi);
    cudaGetSymbolAddress(&ylo, g_ylo);

    conv_x_kernel<<<3072, 256>>>(x);
    transpose_split<<<dim3(72, 24), dim3(32, 8)>>>(Wqkv, (bf16*)wqhi, (bf16*)wqlo, C_DIM, NQKV);
    transpose_split<<<dim3(24, 24), dim3(32, 8)>>>(Wproj, (bf16*)wphi, (bf16*)wplo, C_DIM, C_DIM);
    mma_gemm<0><<<dim3(18, 32), 256>>>((const bf16*)xhi, (const bf16*)xlo, (const bf16*)wqhi,
                                       (const bf16*)wqlo, bqkv, nullptr, NQKV, C_DIM);
    flash_mma<<<dim3(32, H_NUM), 128>>>();
    mma_gemm<1><<<dim3(6, 32), 256>>>((const bf16*)yhi, (const bf16*)ylo, (const bf16*)wphi,
                                      (const bf16*)wplo, bproj, out, C_DIM, C_DIM);
}